// round 8
// baseline (speedup 1.0000x reference)
#include <cuda_runtime.h>
#include <math.h>

#define NPOS 32768      // 32^3 fine positions
#define NCELL 4096      // 16^3 coarse cells
#define CIN 64
#define COFF 81         // 3 * 27 offset channels
#define COUT 32
#define OPAD 84         // 3 sections x 28 (27 padded to 28 for f32x2 pairs)

// Scratch (no allocs allowed -> __device__ globals)
__device__ float g_off[COFF * NPOS];                // offset conv output, [ch][pos]
__device__ float g_weff[8 * CIN * 8 * OPAD];        // [par][c][j][osec*28+oo]
__device__ float g_wT[27 * CIN * COUT];             // main weights [tap][c][oc]
__device__ float g_scale[COUT];
__device__ float g_shift[COUT];

// ---- packed f32x2 helpers -------------------------------------------------
__device__ __forceinline__ unsigned long long pack2(float v) {
    unsigned long long r;
    unsigned u = __float_as_uint(v);
    asm("mov.b64 %0, {%1, %1};" : "=l"(r) : "r"(u));
    return r;
}
__device__ __forceinline__ void fma2(unsigned long long& d,
                                     unsigned long long a,
                                     unsigned long long b) {
    asm("fma.rn.f32x2 %0, %1, %2, %0;" : "+l"(d) : "l"(a), "l"(b));
}
__device__ __forceinline__ float lo2(unsigned long long v) {
    return __uint_as_float((unsigned)(v & 0xffffffffULL));
}
__device__ __forceinline__ float hi2(unsigned long long v) {
    return __uint_as_float((unsigned)(v >> 32));
}

// ---------------------------------------------------------------------------
// K0: transpose main conv weights to [tap][c][oc] (one-time, tiny).
// ---------------------------------------------------------------------------
__global__ void k_wT(const float* __restrict__ wmain) {
    int t = blockIdx.x * blockDim.x + threadIdx.x;
    if (t >= 27 * CIN * COUT) return;
    int oc  = t & 31;
    int c   = (t >> 5) & 63;
    int tap = t >> 11;
    g_wT[t] = wmain[(oc * CIN + c) * 27 + tap];
}

// ---------------------------------------------------------------------------
// K1: parity-combined effective weights, laid out [par][c][j][osec*28+oo]
// so output channels are pair-contiguous for fma.f32x2.
// ---------------------------------------------------------------------------
__global__ void k_weff(const float* __restrict__ w_off) {
    int t = blockIdx.x * blockDim.x + threadIdx.x;
    if (t >= 8 * CIN * 8 * OPAD) return;
    int o84  = t % OPAD;
    int j    = (t / OPAD) & 7;
    int c    = (t / (OPAD * 8)) & 63;
    int par  = t / (OPAD * 8 * CIN);
    int osec = o84 / 28, oo = o84 % 28;
    if (oo >= 27) { g_weff[t] = 0.f; return; }
    int o = osec * 27 + oo;
    int pd = (par >> 2) & 1, ph = (par >> 1) & 1, pw = par & 1;
    int jd = (j >> 2) & 1,  jh = (j >> 1) & 1,  jw = j & 1;
    int sd = jd * (1 + pd), nd = (pd != jd) ? 2 : 1;
    int sh = jh * (1 + ph), nh = (ph != jh) ? 2 : 1;
    int sw = jw * (1 + pw), nw = (pw != jw) ? 2 : 1;
    const float* wb = w_off + (o * CIN + c) * 27;
    float s = 0.f;
    for (int a = 0; a < nd; a++)
        for (int bq = 0; bq < nh; bq++)
            for (int cc = 0; cc < nw; cc++)
                s += wb[(sd + a) * 9 + (sh + bq) * 3 + (sw + cc)];
    g_weff[t] = s;
}

// ---------------------------------------------------------------------------
// K2: offset conv, 3-way oc-split, packed f32x2 accumulation.
// grid = 8 par x 32 tiles x 3 osec = 768 blocks, 128 threads.
// ---------------------------------------------------------------------------
__global__ void __launch_bounds__(128) k_offconv(const float* __restrict__ x,
                                                 const float* __restrict__ b_off) {
    int bid  = blockIdx.x;
    int par  = bid / 96;
    int rest = bid % 96;
    int tile = rest / 3;
    int osec = rest % 3;                      // 27 output channels each
    int q = tile * 128 + threadIdx.x;         // coarse linear index, 0..4095
    int qw = q & 15, qh = (q >> 4) & 15, qd = q >> 8;
    int pd = (par >> 2) & 1, ph = (par >> 1) & 1, pw = par & 1;

    const float* pj[8]; float msk[8];
    #pragma unroll
    for (int j = 0; j < 8; j++) {
        int cd = qd + pd - 1 + ((j >> 2) & 1);
        int ch = qh + ph - 1 + ((j >> 1) & 1);
        int cw = qw + pw - 1 + (j & 1);
        bool v = (unsigned)cd < 16u && (unsigned)ch < 16u && (unsigned)cw < 16u;
        pj[j]  = x + (v ? ((cd * 16 + ch) * 16 + cw) : 0);
        msk[j] = v ? 1.f : 0.f;
    }

    unsigned long long acc2[14];
    #pragma unroll
    for (int i = 0; i < 14; i++) acc2[i] = 0ULL;

    #pragma unroll 2
    for (int c = 0; c < CIN; c++) {
        float xv[8];
        #pragma unroll
        for (int j = 0; j < 8; j++) xv[j] = msk[j] * __ldg(pj[j] + c * NCELL);
        const float* wc = g_weff + ((size_t)(par * CIN + c) * 8) * OPAD + osec * 28;
        #pragma unroll
        for (int j = 0; j < 8; j++) {
            unsigned long long xj = pack2(xv[j]);
            const ulonglong2* wr = (const ulonglong2*)(wc + j * OPAD);
            #pragma unroll
            for (int op = 0; op < 7; op++) {
                ulonglong2 wp = __ldg(wr + op);
                fma2(acc2[2 * op],     xj, wp.x);
                fma2(acc2[2 * op + 1], xj, wp.y);
            }
        }
    }
    int df = 2*qd + pd, hf = 2*qh + ph, wf = 2*qw + pw;
    int p = (df * 32 + hf) * 32 + wf;
    #pragma unroll
    for (int i = 0; i < 14; i++) {
        int o0 = 2 * i, o1 = 2 * i + 1;
        g_off[(osec * 27 + o0) * NPOS + p] = lo2(acc2[i]) + b_off[osec * 27 + o0];
        if (o1 < 27)
            g_off[(osec * 27 + o1) * NPOS + p] = hi2(acc2[i]) + b_off[osec * 27 + o1];
    }
}

// ---------------------------------------------------------------------------
// K3: deformable sampling with corner-dedup + packed f32x2 contraction.
// smem weight staging, 4-way channel split, tree-reduce.
// ---------------------------------------------------------------------------
__global__ void __launch_bounds__(256, 2) k_deform(const float* __restrict__ x,
                                                   const float* __restrict__ bmain,
                                                   float* __restrict__ out) {
    __shared__ __align__(16) float ws[CIN * COUT];  // per-tap weights [c][oc], 8 KB
    __shared__ float red[2 * 64 * 33];              // reduction, padded
    int tid  = threadIdx.x;
    int posi = tid & 63;
    int cs   = tid >> 6;                      // channel quarter 0..3
    int p = blockIdx.x * 64 + posi;
    int wf = p & 31, hf = (p >> 5) & 31, df = p >> 10;

    unsigned long long acc2[16];
    #pragma unroll
    for (int i = 0; i < 16; i++) acc2[i] = 0ULL;

    const float* xbase = x + cs * 16 * NCELL;

    #pragma unroll 1
    for (int tap = 0; tap < 27; tap++) {
        __syncthreads();
        {   // coalesced 8KB copy: g_wT[tap] is contiguous [c][oc]
            const float4* src = (const float4*)(g_wT + tap * CIN * COUT);
            float4* dst = (float4*)ws;
            for (int i = tid; i < CIN * COUT / 4; i += 256) dst[i] = src[i];
        }
        __syncthreads();

        int kd = tap / 9, kh = (tap / 3) % 3, kw = tap % 3;
        float pdc = (float)(df + kd - 1) + __ldg(&g_off[(tap * 3 + 0) * NPOS + p]);
        float phc = (float)(hf + kh - 1) + __ldg(&g_off[(tap * 3 + 1) * NPOS + p]);
        float pwc = (float)(wf + kw - 1) + __ldg(&g_off[(tap * 3 + 2) * NPOS + p]);
        float fd0 = floorf(pdc), fh0 = floorf(phc), fw0 = floorf(pwc);
        int id0 = (int)fd0, ih0 = (int)fh0, iw0 = (int)fw0;
        float fd = pdc - fd0, fh = phc - fh0, fw = pwc - fw0;

        // per-axis coarse slots + folded weights (even base -> single slot)
        int cD[2], cH[2], cW[2]; float wD[2], wH[2], wW[2];
        cD[0] = id0 >> 1; cD[1] = (id0 + 1) >> 1;
        cH[0] = ih0 >> 1; cH[1] = (ih0 + 1) >> 1;
        cW[0] = iw0 >> 1; cW[1] = (iw0 + 1) >> 1;
        bool ed = !(id0 & 1), eh = !(ih0 & 1), ew = !(iw0 & 1);
        wD[0] = ed ? 1.f : 1.f - fd;  wD[1] = ed ? 0.f : fd;
        wH[0] = eh ? 1.f : 1.f - fh;  wH[1] = eh ? 0.f : fh;
        wW[0] = ew ? 1.f : 1.f - fw;  wW[1] = ew ? 0.f : fw;
        if ((unsigned)cD[0] >= 16u) wD[0] = 0.f;
        if ((unsigned)cD[1] >= 16u) wD[1] = 0.f;
        if ((unsigned)cH[0] >= 16u) wH[0] = 0.f;
        if ((unsigned)cH[1] >= 16u) wH[1] = 0.f;
        if ((unsigned)cW[0] >= 16u) wW[0] = 0.f;
        if ((unsigned)cW[1] >= 16u) wW[1] = 0.f;

        float samp[16];
        #pragma unroll
        for (int i = 0; i < 16; i++) samp[i] = 0.f;

        #pragma unroll
        for (int jd = 0; jd < 2; jd++)
        #pragma unroll
        for (int jh = 0; jh < 2; jh++)
        #pragma unroll
        for (int jw = 0; jw < 2; jw++) {
            float wj = wD[jd] * wH[jh] * wW[jw];
            if (wj != 0.f) {
                const float* xb = xbase + ((cD[jd] * 16 + cH[jh]) * 16 + cW[jw]);
                #pragma unroll
                for (int cc = 0; cc < 16; cc++)
                    samp[cc] += wj * __ldg(xb + cc * NCELL);
            }
        }

        // contraction: acc2 pairs += samp[cc] * W[cc][oc-pairs]
        #pragma unroll
        for (int cc = 0; cc < 16; cc++) {
            unsigned long long vp = pack2(samp[cc]);
            const ulonglong2* wrow = (const ulonglong2*)(ws + (cs * 16 + cc) * 32);
            #pragma unroll
            for (int k = 0; k < 8; k++) {
                ulonglong2 wp = wrow[k];
                fma2(acc2[2 * k],     vp, wp.x);
                fma2(acc2[2 * k + 1], vp, wp.y);
            }
        }
    }

    // unpack then tree-reduce across the 4 channel quarters
    float acc[COUT];
    #pragma unroll
    for (int i = 0; i < 16; i++) { acc[2*i] = lo2(acc2[i]); acc[2*i+1] = hi2(acc2[i]); }

    __syncthreads();
    if (cs >= 2) {
        float* dst = red + ((cs - 2) * 64 + posi) * 33;
        #pragma unroll
        for (int oc = 0; oc < COUT; oc++) dst[oc] = acc[oc];
    }
    __syncthreads();
    if (cs < 2) {
        const float* src = red + (cs * 64 + posi) * 33;
        #pragma unroll
        for (int oc = 0; oc < COUT; oc++) acc[oc] += src[oc];
    }
    __syncthreads();
    if (cs == 1) {
        float* dst = red + posi * 33;
        #pragma unroll
        for (int oc = 0; oc < COUT; oc++) dst[oc] = acc[oc];
    }
    __syncthreads();
    if (cs == 0) {
        const float* src = red + posi * 33;
        #pragma unroll
        for (int oc = 0; oc < COUT; oc++)
            out[oc * NPOS + p] = acc[oc] + src[oc] + bmain[oc];
    }
}

// ---------------------------------------------------------------------------
// K4a: per-channel mean/var -> scale/shift.  K4b: normalize + ReLU in place.
// ---------------------------------------------------------------------------
__global__ void __launch_bounds__(1024) k_bnstat(const float* __restrict__ out,
                                                 const float* __restrict__ gamma,
                                                 const float* __restrict__ beta) {
    __shared__ float ssum[1024], ssq[1024];
    int ch = blockIdx.x;
    const float* base = out + ch * NPOS;
    float s = 0.f, sq = 0.f;
    for (int i = threadIdx.x; i < NPOS; i += 1024) {
        float v = base[i];
        s += v; sq += v * v;
    }
    ssum[threadIdx.x] = s; ssq[threadIdx.x] = sq;
    __syncthreads();
    for (int st = 512; st > 0; st >>= 1) {
        if (threadIdx.x < st) {
            ssum[threadIdx.x] += ssum[threadIdx.x + st];
            ssq[threadIdx.x]  += ssq[threadIdx.x + st];
        }
        __syncthreads();
    }
    if (threadIdx.x == 0) {
        float mean = ssum[0] * (1.f / (float)NPOS);
        float var  = ssq[0] * (1.f / (float)NPOS) - mean * mean;
        float inv  = rsqrtf(var + 1e-5f);
        float a = gamma[ch] * inv;
        g_scale[ch] = a;
        g_shift[ch] = beta[ch] - mean * a;
    }
}

__global__ void k_bnapply(float* __restrict__ out) {
    int idx = blockIdx.x * 256 + threadIdx.x;
    int ch = idx >> 15;
    float v = out[idx] * g_scale[ch] + g_shift[ch];
    out[idx] = fmaxf(v, 0.f);
}

extern "C" void kernel_launch(void* const* d_in, const int* in_sizes, int n_in,
                              void* d_out, int out_size) {
    const float* x     = (const float*)d_in[0];   // (1,64,16,16,16)
    const float* w_off = (const float*)d_in[1];   // (81,64,3,3,3)
    const float* b_off = (const float*)d_in[2];   // (81,)
    const float* w     = (const float*)d_in[3];   // (32,64,3,3,3)
    const float* b     = (const float*)d_in[4];   // (32,)
    const float* gamma = (const float*)d_in[5];   // (32,)
    const float* beta  = (const float*)d_in[6];   // (32,)
    float* out = (float*)d_out;                   // (1,32,32,32,32)

    k_wT<<<(27 * CIN * COUT + 255) / 256, 256>>>(w);
    k_weff<<<(8 * CIN * 8 * OPAD + 255) / 256, 256>>>(w_off);
    k_offconv<<<768, 128>>>(x, b_off);
    k_deform<<<512, 256>>>(x, b, out);
    k_bnstat<<<COUT, 1024>>>(out, gamma, beta);
    k_bnapply<<<4096, 256>>>(out);
}